// round 2
// baseline (speedup 1.0000x reference)
#include <cuda_runtime.h>
#include <cstdint>

#define N_NODES   100000
#define F_IN      65
#define F_HID     64
#define F_OUT     64

// Scratch: agg[node][feat] = x[node] + sum_{edges: dst==node} x[src]
__device__ __align__(16) float g_agg[(size_t)N_NODES * F_IN];
// 1 if edge_index is genuinely int64 on device, 0 if it was stored as int32
__device__ int g_idx_is64;

// ---------------------------------------------------------------------------
// Kernel 1: init agg = x (folds in the (1+eps)*x term), also reset dtype flag
// ---------------------------------------------------------------------------
__global__ void init_agg_kernel(const float* __restrict__ x, int n_elts4) {
    int i = blockIdx.x * blockDim.x + threadIdx.x;
    if (i == 0) g_idx_is64 = 1;
    if (i < n_elts4) {
        reinterpret_cast<float4*>(g_agg)[i] =
            reinterpret_cast<const float4*>(x)[i];
    }
}

// ---------------------------------------------------------------------------
// Kernel 2: dtype probe. Interpret buffer as int64; any out-of-range value
// proves the data is actually int32 (pairs fuse to >= 2^32 almost surely).
// ---------------------------------------------------------------------------
__global__ void detect_dtype_kernel(const long long* __restrict__ ei, int n64) {
    int stride = gridDim.x * blockDim.x;
    bool bad = false;
    for (int i = blockIdx.x * blockDim.x + threadIdx.x; i < n64; i += stride) {
        long long v = ei[i];
        bad |= (v < 0) | (v >= N_NODES);
    }
    if (__syncthreads_or(bad) && threadIdx.x == 0) g_idx_is64 = 0;
}

// ---------------------------------------------------------------------------
// Kernel 3: scatter-add. One warp per edge; lanes cover the 65 features.
// ---------------------------------------------------------------------------
__global__ void scatter_kernel(const float* __restrict__ x,
                               const void* __restrict__ edge_index,
                               int n_edges) {
    int warp = (blockIdx.x * blockDim.x + threadIdx.x) >> 5;
    int lane = threadIdx.x & 31;
    if (warp >= n_edges) return;

    int src, dst;
    if (g_idx_is64) {
        const long long* ei = (const long long*)edge_index;
        src = (int)ei[warp];
        dst = (int)ei[(size_t)n_edges + warp];
    } else {
        const int* ei = (const int*)edge_index;
        src = ei[warp];
        dst = ei[n_edges + warp];
    }

    const float* xr = x + (size_t)src * F_IN;
    float*       ar = g_agg + (size_t)dst * F_IN;

    #pragma unroll
    for (int f = lane; f < F_IN; f += 32) {
        atomicAdd(&ar[f], __ldg(&xr[f]));
    }
}

// ---------------------------------------------------------------------------
// Kernel 4: fused MLP.  out = relu(h@W1 + b1) @ W2 + b2, h = g_agg row.
// Persistent blocks: weights in shared once, grid-stride over 4-node tiles.
// ---------------------------------------------------------------------------
#define MLP_BLOCK 256
#define NODES_PER_TILE 4

__global__ void mlp_kernel(const float* __restrict__ W1,
                           const float* __restrict__ b1,
                           const float* __restrict__ W2,
                           const float* __restrict__ b2,
                           float* __restrict__ out,
                           int n_nodes) {
    __shared__ float sW1[F_IN * F_HID];
    __shared__ float sW2[F_HID * F_OUT];
    __shared__ float sb1[F_HID];
    __shared__ float sb2[F_OUT];
    __shared__ float sh[NODES_PER_TILE][F_IN];
    __shared__ float sh2[NODES_PER_TILE][F_HID];

    int tid = threadIdx.x;
    for (int i = tid; i < F_IN * F_HID; i += MLP_BLOCK)  sW1[i] = W1[i];
    for (int i = tid; i < F_HID * F_OUT; i += MLP_BLOCK) sW2[i] = W2[i];
    if (tid < F_HID) { sb1[tid] = b1[tid]; sb2[tid] = b2[tid]; }
    __syncthreads();

    int g = tid >> 6;        // node within tile (0..3)
    int j = tid & 63;        // output feature

    for (int base = blockIdx.x * NODES_PER_TILE; base < n_nodes;
         base += gridDim.x * NODES_PER_TILE) {
        int node = base + g;

        if (node < n_nodes) {
            const float* hr = g_agg + (size_t)node * F_IN;
            sh[g][j] = hr[j];
            if (j == 0) sh[g][64] = hr[64];
        }
        __syncthreads();

        float acc = sb1[j];
        #pragma unroll
        for (int k = 0; k < F_IN; k++) acc = fmaf(sh[g][k], sW1[k * F_HID + j], acc);
        sh2[g][j] = fmaxf(acc, 0.0f);
        __syncthreads();

        float acc2 = sb2[j];
        #pragma unroll
        for (int k = 0; k < F_HID; k++) acc2 = fmaf(sh2[g][k], sW2[k * F_OUT + j], acc2);

        if (node < n_nodes) out[(size_t)node * F_OUT + j] = acc2;
        __syncthreads();
    }
}

// ---------------------------------------------------------------------------
extern "C" void kernel_launch(void* const* d_in, const int* in_sizes, int n_in,
                              void* d_out, int out_size) {
    const float* x  = (const float*)d_in[0];   // [100000, 65]
    const void*  ei = d_in[1];                 // [2, E], int64 OR int32 (probed)
    const float* W1 = (const float*)d_in[2];   // [65, 64]
    const float* b1 = (const float*)d_in[3];   // [64]
    const float* W2 = (const float*)d_in[4];   // [64, 64]
    const float* b2 = (const float*)d_in[5];   // [64]
    float*       out = (float*)d_out;          // [100000, 64]

    // element count of edge_index tensor (2*E regardless of dtype)
    int n_elems = in_sizes[1];
    int n_edges = n_elems / 2;

    // 1) agg = x ; reset flag
    int n4 = (N_NODES * F_IN) / 4;
    init_agg_kernel<<<(n4 + 255) / 256, 256>>>(x, n4);

    // 2) probe index dtype (reads buffer as int64: n_elems/2 values covers
    //    the whole buffer if int64, half if int32 — enough either way)
    detect_dtype_kernel<<<1024, 256>>>((const long long*)ei, n_elems / 2);

    // 3) scatter-add: warp per edge
    int warps_per_block = 8;
    int blocks = (n_edges + warps_per_block - 1) / warps_per_block;
    scatter_kernel<<<blocks, warps_per_block * 32>>>(x, ei, n_edges);

    // 4) fused MLP
    mlp_kernel<<<1024, MLP_BLOCK>>>(W1, b1, W2, b2, out, N_NODES);
}

// round 4
// speedup vs baseline: 1.5203x; 1.5203x over previous
#include <cuda_runtime.h>
#include <cstdint>

#define N_NODES   100000
#define F_IN      65
#define F_PAD     68      // padded agg row: 17 aligned float4 chunks
#define F_HID     64
#define F_OUT     64

// ---- scratch: ONE big buffer (27.2MB) + flag. Keep footprint small: the
// harness's memory checkpoint trips on large lazy-loaded global segments. ----
__device__ __align__(16) float g_agg[(size_t)N_NODES * F_PAD];
__device__ int g_idx_is64;

// ---------------------------------------------------------------------------
// Kernel 1: agg = x (padded; folds the (1+eps)*x term). Resets dtype flag.
// ---------------------------------------------------------------------------
__global__ void init_pad_kernel(const float* __restrict__ x) {
    int i = blockIdx.x * blockDim.x + threadIdx.x;
    if (i == 0) g_idx_is64 = 1;
    const int total = N_NODES * F_PAD;
    if (i >= total) return;
    int node = i / F_PAD;
    int col  = i - node * F_PAD;
    g_agg[i] = (col < F_IN) ? x[(size_t)node * F_IN + col] : 0.0f;
}

// ---------------------------------------------------------------------------
// Kernel 2: dtype probe — any value outside [0, N_NODES) when read as int64
// means the buffer actually holds int32 indices.
// ---------------------------------------------------------------------------
__global__ void detect_dtype_kernel(const long long* __restrict__ ei, int n64) {
    int stride = gridDim.x * blockDim.x;
    bool bad = false;
    for (int i = blockIdx.x * blockDim.x + threadIdx.x; i < n64; i += stride) {
        long long v = ei[i];
        bad |= (v < 0) | (v >= N_NODES);
    }
    if (__syncthreads_or(bad) && threadIdx.x == 0) g_idx_is64 = 0;
}

// ---------------------------------------------------------------------------
// Kernel 3: scatter-add. 17 lanes per edge; each lane gathers 4 scalars from
// x[src] (unaligned source is fine scalar-wise) and issues ONE
// red.global.add.v4.f32 into the 16B-aligned padded agg row.
// Padded cols 65..67 receive +0 (harmless).
// ---------------------------------------------------------------------------
__global__ void scatter_kernel(const float* __restrict__ x,
                               const void* __restrict__ edge_index,
                               int n_edges, int n_work) {
    int idx = blockIdx.x * blockDim.x + threadIdx.x;
    if (idx >= n_work) return;
    int e = idx / 17;
    int q = idx - e * 17;

    int src, dst;
    if (g_idx_is64) {
        const long long* p = (const long long*)edge_index;
        src = (int)p[e];
        dst = (int)p[(size_t)n_edges + e];
    } else {
        const int* p = (const int*)edge_index;
        src = p[e];
        dst = p[n_edges + e];
    }

    const float* xr = x + (size_t)src * F_IN + q * 4;
    float v0, v1, v2, v3;
    if (q < 16) {
        v0 = __ldg(xr + 0); v1 = __ldg(xr + 1);
        v2 = __ldg(xr + 2); v3 = __ldg(xr + 3);
    } else {            // cols 64..67: only 64 is real
        v0 = __ldg(xr + 0); v1 = 0.f; v2 = 0.f; v3 = 0.f;
    }

    float* addr = &g_agg[(size_t)dst * F_PAD + q * 4];
    asm volatile("red.global.add.v4.f32 [%0], {%1, %2, %3, %4};"
                 :: "l"(addr), "f"(v0), "f"(v1), "f"(v2), "f"(v3)
                 : "memory");
}

// ---------------------------------------------------------------------------
// Kernel 4: fused 2-layer MLP.  out = relu(agg@W1+b1)@W2 + b2.
// Block = 32 rows x full 64 hidden x full 64 out; 256 threads, 2x4 register
// tiles per layer. Layer-1 output lives in shared (aliases the A-tile).
// Static smem ~42KB.
// ---------------------------------------------------------------------------
#define MROWS 32

__global__ void mlp_fused_kernel(const float* __restrict__ W1,
                                 const float* __restrict__ b1,
                                 const float* __restrict__ W2,
                                 const float* __restrict__ b2,
                                 float* __restrict__ out,
                                 int n) {
    // shAB: first used as A-tile transposed [k][r] (stride 32, k<68),
    //       then reused as h1 transposed [k][r] (stride 34, k<64). 68*32=2176.
    __shared__ __align__(16) float shAB[68 * 32];
    __shared__ __align__(16) float shW1[F_IN * F_HID];    // [k][j]
    __shared__ __align__(16) float shW2[F_HID * F_OUT];   // [k][j]
    __shared__ float sb1[F_HID];
    __shared__ float sb2[F_OUT];

    int tid  = threadIdx.x;
    int row0 = blockIdx.x * MROWS;

    // ---- load A tile transposed: 32 rows x 17 float4 chunks = 544 loads ----
    for (int t = tid; t < MROWS * 17; t += 256) {
        int r = t / 17;
        int q = t - r * 17;
        int row = row0 + r;
        float4 v = make_float4(0.f, 0.f, 0.f, 0.f);
        if (row < n)
            v = *reinterpret_cast<const float4*>(&g_agg[(size_t)row * F_PAD + q * 4]);
        shAB[(q * 4 + 0) * 32 + r] = v.x;
        shAB[(q * 4 + 1) * 32 + r] = v.y;
        shAB[(q * 4 + 2) * 32 + r] = v.z;
        shAB[(q * 4 + 3) * 32 + r] = v.w;
    }
    for (int t = tid; t < F_IN * F_HID; t += 256)  shW1[t] = W1[t];
    for (int t = tid; t < F_HID * F_OUT; t += 256) shW2[t] = W2[t];
    if (tid < F_HID) { sb1[tid] = b1[tid]; sb2[tid] = b2[tid]; }
    __syncthreads();

    int ty = tid >> 4;   // 0..15 -> rows ty*2, ty*2+1
    int tx = tid & 15;   // 0..15 -> cols tx*4..tx*4+3

    // ---- layer 1: h1 = relu(A @ W1 + b1) ----
    float acc[2][4];
    {
        float4 b = *reinterpret_cast<const float4*>(&sb1[tx * 4]);
        acc[0][0] = b.x; acc[0][1] = b.y; acc[0][2] = b.z; acc[0][3] = b.w;
        acc[1][0] = b.x; acc[1][1] = b.y; acc[1][2] = b.z; acc[1][3] = b.w;
    }
    #pragma unroll 5
    for (int k = 0; k < F_IN; k++) {
        float2 a = *reinterpret_cast<const float2*>(&shAB[k * 32 + ty * 2]);
        float4 b = *reinterpret_cast<const float4*>(&shW1[k * F_HID + tx * 4]);
        acc[0][0] = fmaf(a.x, b.x, acc[0][0]);
        acc[0][1] = fmaf(a.x, b.y, acc[0][1]);
        acc[0][2] = fmaf(a.x, b.z, acc[0][2]);
        acc[0][3] = fmaf(a.x, b.w, acc[0][3]);
        acc[1][0] = fmaf(a.y, b.x, acc[1][0]);
        acc[1][1] = fmaf(a.y, b.y, acc[1][1]);
        acc[1][2] = fmaf(a.y, b.z, acc[1][2]);
        acc[1][3] = fmaf(a.y, b.w, acc[1][3]);
    }
    __syncthreads();   // A-tile reads done; shAB now becomes h1 storage

    // write h1 transposed [col][row], stride 34 (64*34=2176, keeps 8B align)
    #pragma unroll
    for (int c = 0; c < 4; c++) {
        int col = tx * 4 + c;
        shAB[col * 34 + ty * 2 + 0] = fmaxf(acc[0][c], 0.f);
        shAB[col * 34 + ty * 2 + 1] = fmaxf(acc[1][c], 0.f);
    }
    __syncthreads();

    // ---- layer 2: out = h1 @ W2 + b2 ----
    float acc2[2][4];
    {
        float4 b = *reinterpret_cast<const float4*>(&sb2[tx * 4]);
        acc2[0][0] = b.x; acc2[0][1] = b.y; acc2[0][2] = b.z; acc2[0][3] = b.w;
        acc2[1][0] = b.x; acc2[1][1] = b.y; acc2[1][2] = b.z; acc2[1][3] = b.w;
    }
    #pragma unroll 8
    for (int k = 0; k < F_HID; k++) {
        float2 a = *reinterpret_cast<const float2*>(&shAB[k * 34 + ty * 2]);
        float4 b = *reinterpret_cast<const float4*>(&shW2[k * F_OUT + tx * 4]);
        acc2[0][0] = fmaf(a.x, b.x, acc2[0][0]);
        acc2[0][1] = fmaf(a.x, b.y, acc2[0][1]);
        acc2[0][2] = fmaf(a.x, b.z, acc2[0][2]);
        acc2[0][3] = fmaf(a.x, b.w, acc2[0][3]);
        acc2[1][0] = fmaf(a.y, b.x, acc2[1][0]);
        acc2[1][1] = fmaf(a.y, b.y, acc2[1][1]);
        acc2[1][2] = fmaf(a.y, b.z, acc2[1][2]);
        acc2[1][3] = fmaf(a.y, b.w, acc2[1][3]);
    }

    #pragma unroll
    for (int i = 0; i < 2; i++) {
        int row = row0 + ty * 2 + i;
        if (row < n) {
            float4 o = make_float4(acc2[i][0], acc2[i][1], acc2[i][2], acc2[i][3]);
            *reinterpret_cast<float4*>(&out[(size_t)row * F_OUT + tx * 4]) = o;
        }
    }
}

// ---------------------------------------------------------------------------
extern "C" void kernel_launch(void* const* d_in, const int* in_sizes, int n_in,
                              void* d_out, int out_size) {
    const float* x  = (const float*)d_in[0];   // [100000, 65]
    const void*  ei = d_in[1];                 // [2, E] int64 or int32 (probed)
    const float* W1 = (const float*)d_in[2];   // [65, 64]
    const float* b1 = (const float*)d_in[3];   // [64]
    const float* W2 = (const float*)d_in[4];   // [64, 64]
    const float* b2 = (const float*)d_in[5];   // [64]
    float*       out = (float*)d_out;          // [100000, 64]

    int n_elems = in_sizes[1];     // 2*E elements, dtype unknown
    int n_edges = n_elems / 2;

    // 1) padded agg = x (+flag reset)
    int total = N_NODES * F_PAD;
    init_pad_kernel<<<(total + 255) / 256, 256>>>(x);

    // 2) dtype probe
    detect_dtype_kernel<<<1024, 256>>>((const long long*)ei, n_elems / 2);

    // 3) vectorized scatter-add (17 lanes/edge)
    int n_work = n_edges * 17;
    scatter_kernel<<<(n_work + 255) / 256, 256>>>(x, ei, n_edges, n_work);

    // 4) fused 2-layer MLP
    int nblk = (N_NODES + MROWS - 1) / MROWS;
    mlp_fused_kernel<<<nblk, 256>>>(W1, b1, W2, b2, out, N_NODES);
}

// round 5
// speedup vs baseline: 1.9286x; 1.2686x over previous
#include <cuda_runtime.h>
#include <cstdint>

#define N_NODES   100000
#define F_IN      65
#define F_HID     64
#define F_OUT     64

// ---- scratch: ONE buffer (25.6MB) + flag. Keep static footprint minimal:
// the harness memory checkpoint trips on large lazy-loaded global segments. --
__device__ __align__(16) float g_y[(size_t)N_NODES * F_HID];   // y = x @ W1
__device__ int g_idx_is64;

// ---------------------------------------------------------------------------
// Kernel 1: zero d_out (it becomes the aggregation accumulator) + reset flag.
// ---------------------------------------------------------------------------
__global__ void zero_out_kernel(float4* __restrict__ out, int n4) {
    int i = blockIdx.x * blockDim.x + threadIdx.x;
    if (i == 0) g_idx_is64 = 1;
    if (i < n4) out[i] = make_float4(0.f, 0.f, 0.f, 0.f);
}

// ---------------------------------------------------------------------------
// Kernel 2: dtype probe — any value outside [0, N_NODES) read as int64 means
// the buffer actually holds int32 indices.
// ---------------------------------------------------------------------------
__global__ void detect_dtype_kernel(const long long* __restrict__ ei, int n64) {
    int stride = gridDim.x * blockDim.x;
    bool bad = false;
    for (int i = blockIdx.x * blockDim.x + threadIdx.x; i < n64; i += stride) {
        long long v = ei[i];
        bad |= (v < 0) | (v >= N_NODES);
    }
    if (__syncthreads_or(bad) && threadIdx.x == 0) g_idx_is64 = 0;
}

// ---------------------------------------------------------------------------
// Kernel 3: GEMM1  y = x @ W1  (no bias, no activation).
// Block = 64 rows x 64 cols, 256 threads, 4x4 register tile.
// A kept row-major [r][68] in shared; a-operands are broadcast scalar LDS.
// ---------------------------------------------------------------------------
__global__ void gemm1_kernel(const float* __restrict__ x,
                             const float* __restrict__ W1,
                             int n) {
    __shared__ float shA[64 * 68];                     // [r][k], stride 68
    __shared__ __align__(16) float shW[F_IN * F_HID];  // [k][j]

    int tid  = threadIdx.x;
    int row0 = blockIdx.x * 64;

    // A tile: 64 rows x 65 cols, coalesced-by-row scalar loads
    for (int t = tid; t < 64 * F_IN; t += 256) {
        int r = t / F_IN;
        int c = t - r * F_IN;
        int row = row0 + r;
        shA[r * 68 + c] = (row < n) ? x[(size_t)row * F_IN + c] : 0.f;
    }
    for (int t = tid; t < F_IN * F_HID; t += 256) shW[t] = W1[t];
    __syncthreads();

    int ty = tid >> 4;   // 0..15 -> rows ty*4..+3
    int tx = tid & 15;   // 0..15 -> cols tx*4..+3

    float acc[4][4];
    #pragma unroll
    for (int i = 0; i < 4; i++)
        #pragma unroll
        for (int j = 0; j < 4; j++) acc[i][j] = 0.f;

    const float* ar = &shA[(ty * 4) * 68];
    #pragma unroll 5
    for (int k = 0; k < F_IN; k++) {
        float a0 = ar[0 * 68 + k];
        float a1 = ar[1 * 68 + k];
        float a2 = ar[2 * 68 + k];
        float a3 = ar[3 * 68 + k];
        float4 b = *reinterpret_cast<const float4*>(&shW[k * F_HID + tx * 4]);
        acc[0][0] = fmaf(a0, b.x, acc[0][0]); acc[0][1] = fmaf(a0, b.y, acc[0][1]);
        acc[0][2] = fmaf(a0, b.z, acc[0][2]); acc[0][3] = fmaf(a0, b.w, acc[0][3]);
        acc[1][0] = fmaf(a1, b.x, acc[1][0]); acc[1][1] = fmaf(a1, b.y, acc[1][1]);
        acc[1][2] = fmaf(a1, b.z, acc[1][2]); acc[1][3] = fmaf(a1, b.w, acc[1][3]);
        acc[2][0] = fmaf(a2, b.x, acc[2][0]); acc[2][1] = fmaf(a2, b.y, acc[2][1]);
        acc[2][2] = fmaf(a2, b.z, acc[2][2]); acc[2][3] = fmaf(a2, b.w, acc[2][3]);
        acc[3][0] = fmaf(a3, b.x, acc[3][0]); acc[3][1] = fmaf(a3, b.y, acc[3][1]);
        acc[3][2] = fmaf(a3, b.z, acc[3][2]); acc[3][3] = fmaf(a3, b.w, acc[3][3]);
    }

    #pragma unroll
    for (int i = 0; i < 4; i++) {
        int row = row0 + ty * 4 + i;
        if (row < n) {
            float4 o = make_float4(acc[i][0], acc[i][1], acc[i][2], acc[i][3]);
            *reinterpret_cast<float4*>(&g_y[(size_t)row * F_HID + tx * 4]) = o;
        }
    }
}

// ---------------------------------------------------------------------------
// Kernel 4: scatter-add in projected space.  acc[dst] += y[src]  (into d_out)
// 16 lanes per edge: one aligned LDG.128 gather + one red.global.add.v4.f32.
// ---------------------------------------------------------------------------
__global__ void scatter_kernel(float* __restrict__ acc,
                               const void* __restrict__ edge_index,
                               int n_edges, int n_work) {
    int idx = blockIdx.x * blockDim.x + threadIdx.x;
    if (idx >= n_work) return;
    int e = idx >> 4;
    int q = idx & 15;

    int src, dst;
    if (g_idx_is64) {
        const long long* p = (const long long*)edge_index;
        src = (int)p[e];
        dst = (int)p[(size_t)n_edges + e];
    } else {
        const int* p = (const int*)edge_index;
        src = p[e];
        dst = p[n_edges + e];
    }

    float4 v = *reinterpret_cast<const float4*>(&g_y[(size_t)src * F_HID + q * 4]);
    float* addr = &acc[(size_t)dst * F_HID + q * 4];
    asm volatile("red.global.add.v4.f32 [%0], {%1, %2, %3, %4};"
                 :: "l"(addr), "f"(v.x), "f"(v.y), "f"(v.z), "f"(v.w)
                 : "memory");
}

// ---------------------------------------------------------------------------
// Kernel 5: GEMM2 (fused, in-place on d_out):
//   out = relu(y + acc + b1) @ W2 + b2
// Block reads its own 64 rows of y and d_out into shared, then overwrites.
// ---------------------------------------------------------------------------
__global__ void gemm2_kernel(const float* __restrict__ W2,
                             const float* __restrict__ b1,
                             const float* __restrict__ b2,
                             float* __restrict__ out,
                             int n) {
    __shared__ __align__(16) float shA[64 * 68];        // relu(y+acc+b1), [r][k]
    __shared__ __align__(16) float shW[F_HID * F_OUT];  // [k][j]
    __shared__ float sb1[F_HID];
    __shared__ float sb2[F_OUT];

    int tid  = threadIdx.x;
    int row0 = blockIdx.x * 64;

    if (tid < F_HID) { sb1[tid] = b1[tid]; sb2[tid] = b2[tid]; }
    for (int t = tid; t < F_HID * F_OUT; t += 256) shW[t] = W2[t];
    __syncthreads();   // sb1 needed below

    // Build A = relu(y + acc + b1): 64 rows x 16 float4 quads, coalesced
    for (int t = tid; t < 64 * 16; t += 256) {
        int r = t >> 4;
        int q = t & 15;
        int row = row0 + r;
        float4 o = make_float4(0.f, 0.f, 0.f, 0.f);
        if (row < n) {
            float4 yv = *reinterpret_cast<const float4*>(&g_y[(size_t)row * F_HID + q * 4]);
            float4 av = *reinterpret_cast<const float4*>(&out[(size_t)row * F_HID + q * 4]);
            float4 bv = *reinterpret_cast<const float4*>(&sb1[q * 4]);
            o.x = fmaxf(yv.x + av.x + bv.x, 0.f);
            o.y = fmaxf(yv.y + av.y + bv.y, 0.f);
            o.z = fmaxf(yv.z + av.z + bv.z, 0.f);
            o.w = fmaxf(yv.w + av.w + bv.w, 0.f);
        }
        *reinterpret_cast<float4*>(&shA[r * 68 + q * 4]) = o;
    }
    __syncthreads();

    int ty = tid >> 4;
    int tx = tid & 15;

    float acc[4][4];
    {
        float4 b = *reinterpret_cast<const float4*>(&sb2[tx * 4]);
        #pragma unroll
        for (int i = 0; i < 4; i++) {
            acc[i][0] = b.x; acc[i][1] = b.y; acc[i][2] = b.z; acc[i][3] = b.w;
        }
    }

    const float* ar = &shA[(ty * 4) * 68];
    #pragma unroll 8
    for (int k = 0; k < F_HID; k++) {
        float a0 = ar[0 * 68 + k];
        float a1 = ar[1 * 68 + k];
        float a2 = ar[2 * 68 + k];
        float a3 = ar[3 * 68 + k];
        float4 b = *reinterpret_cast<const float4*>(&shW[k * F_OUT + tx * 4]);
        acc[0][0] = fmaf(a0, b.x, acc[0][0]); acc[0][1] = fmaf(a0, b.y, acc[0][1]);
        acc[0][2] = fmaf(a0, b.z, acc[0][2]); acc[0][3] = fmaf(a0, b.w, acc[0][3]);
        acc[1][0] = fmaf(a1, b.x, acc[1][0]); acc[1][1] = fmaf(a1, b.y, acc[1][1]);
        acc[1][2] = fmaf(a1, b.z, acc[1][2]); acc[1][3] = fmaf(a1, b.w, acc[1][3]);
        acc[2][0] = fmaf(a2, b.x, acc[2][0]); acc[2][1] = fmaf(a2, b.y, acc[2][1]);
        acc[2][2] = fmaf(a2, b.z, acc[2][2]); acc[2][3] = fmaf(a2, b.w, acc[2][3]);
        acc[3][0] = fmaf(a3, b.x, acc[3][0]); acc[3][1] = fmaf(a3, b.y, acc[3][1]);
        acc[3][2] = fmaf(a3, b.z, acc[3][2]); acc[3][3] = fmaf(a3, b.w, acc[3][3]);
    }

    #pragma unroll
    for (int i = 0; i < 4; i++) {
        int row = row0 + ty * 4 + i;
        if (row < n) {
            float4 o = make_float4(acc[i][0], acc[i][1], acc[i][2], acc[i][3]);
            *reinterpret_cast<float4*>(&out[(size_t)row * F_OUT + tx * 4]) = o;
        }
    }
}

// ---------------------------------------------------------------------------
extern "C" void kernel_launch(void* const* d_in, const int* in_sizes, int n_in,
                              void* d_out, int out_size) {
    const float* x  = (const float*)d_in[0];   // [100000, 65]
    const void*  ei = d_in[1];                 // [2, E] int64 or int32 (probed)
    const float* W1 = (const float*)d_in[2];   // [65, 64]
    const float* b1 = (const float*)d_in[3];   // [64]
    const float* W2 = (const float*)d_in[4];   // [64, 64]
    const float* b2 = (const float*)d_in[5];   // [64]
    float*       out = (float*)d_out;          // [100000, 64]

    int n_elems = in_sizes[1];
    int n_edges = n_elems / 2;

    // 1) out = 0 (aggregation accumulator) + flag reset
    int n4 = (N_NODES * F_HID) / 4;
    zero_out_kernel<<<(n4 + 255) / 256, 256>>>((float4*)out, n4);

    // 2) index dtype probe
    detect_dtype_kernel<<<1024, 256>>>((const long long*)ei, n_elems / 2);

    // 3) y = x @ W1
    int nblk = (N_NODES + 63) / 64;
    gemm1_kernel<<<nblk, 256>>>(x, W1, N_NODES);

    // 4) out[dst] += y[src]  (16 lanes/edge, vector REDs)
    int n_work = n_edges * 16;
    scatter_kernel<<<(n_work + 255) / 256, 256>>>(out, ei, n_edges, n_work);

    // 5) out = relu(y + out + b1) @ W2 + b2   (in-place)
    gemm2_kernel<<<nblk, 256>>>(W2, b1, b2, out, N_NODES);
}

// round 6
// speedup vs baseline: 1.9948x; 1.0343x over previous
#include <cuda_runtime.h>
#include <cstdint>

#define N_NODES   100000
#define F_IN      65
#define F_HID     64
#define F_OUT     64

// ---- scratch: ONE buffer (25.6MB) + flag (memory-checkpoint-safe) ---------
__device__ __align__(16) float g_y[(size_t)N_NODES * F_HID];   // y = x @ W1
__device__ int g_idx_is64;

// ---------------------------------------------------------------------------
// Kernel 1: zero d_out (aggregation accumulator) + reset dtype flag.
// ---------------------------------------------------------------------------
__global__ void zero_out_kernel(float4* __restrict__ out, int n4) {
    int i = blockIdx.x * blockDim.x + threadIdx.x;
    if (i == 0) g_idx_is64 = 1;
    if (i < n4) out[i] = make_float4(0.f, 0.f, 0.f, 0.f);
}

// ---------------------------------------------------------------------------
// Kernel 2: dtype probe — any value outside [0, N_NODES) read as int64 means
// the buffer actually holds int32 indices.
// ---------------------------------------------------------------------------
__global__ void detect_dtype_kernel(const long long* __restrict__ ei, int n64) {
    int stride = gridDim.x * blockDim.x;
    bool bad = false;
    for (int i = blockIdx.x * blockDim.x + threadIdx.x; i < n64; i += stride) {
        long long v = ei[i];
        bad |= (v < 0) | (v >= N_NODES);
    }
    if (__syncthreads_or(bad) && threadIdx.x == 0) g_idx_is64 = 0;
}

// ---------------------------------------------------------------------------
// Kernel 3: GEMM1  y = x @ W1.  128 rows x 64 cols per block, 256 threads,
// 8x4 register tile. A row-major in shared (conflict-free); a-operands are
// broadcast scalar LDS; b streamed from L1 via __ldg (W1 is 16KB, L1-resident).
// ---------------------------------------------------------------------------
#define GROWS 128

__global__ void gemm1_kernel(const float* __restrict__ x,
                             const float* __restrict__ W1,
                             int n) {
    __shared__ float shA[GROWS * 68];   // [r][k], stride 68

    int tid  = threadIdx.x;
    int row0 = blockIdx.x * GROWS;

    for (int t = tid; t < GROWS * F_IN; t += 256) {
        int r = t / F_IN;
        int c = t - r * F_IN;
        int row = row0 + r;
        shA[r * 68 + c] = (row < n) ? x[(size_t)row * F_IN + c] : 0.f;
    }
    __syncthreads();

    int ty = tid >> 4;   // 0..15 -> rows ty*8 .. +7
    int tx = tid & 15;   // 0..15 -> cols tx*4 .. +3

    float acc[8][4];
    #pragma unroll
    for (int i = 0; i < 8; i++)
        #pragma unroll
        for (int j = 0; j < 4; j++) acc[i][j] = 0.f;

    const float* ar = &shA[(ty * 8) * 68];
    #pragma unroll 5
    for (int k = 0; k < F_IN; k++) {
        float4 b = __ldg(reinterpret_cast<const float4*>(&W1[k * F_HID + tx * 4]));
        float a[8];
        #pragma unroll
        for (int i = 0; i < 8; i++) a[i] = ar[i * 68 + k];
        #pragma unroll
        for (int i = 0; i < 8; i++) {
            acc[i][0] = fmaf(a[i], b.x, acc[i][0]);
            acc[i][1] = fmaf(a[i], b.y, acc[i][1]);
            acc[i][2] = fmaf(a[i], b.z, acc[i][2]);
            acc[i][3] = fmaf(a[i], b.w, acc[i][3]);
        }
    }

    #pragma unroll
    for (int i = 0; i < 8; i++) {
        int row = row0 + ty * 8 + i;
        if (row < n) {
            float4 o = make_float4(acc[i][0], acc[i][1], acc[i][2], acc[i][3]);
            *reinterpret_cast<float4*>(&g_y[(size_t)row * F_HID + tx * 4]) = o;
        }
    }
}

// ---------------------------------------------------------------------------
// Kernel 4: scatter-add, 4 edges per thread (MLP=4), vectorized index loads.
// 16 lanes per edge-quad: lane q handles quad q of 4 consecutive edges.
// ---------------------------------------------------------------------------
__global__ void scatter_kernel(float* __restrict__ acc,
                               const void* __restrict__ edge_index,
                               int n_edges, int n_groups) {
    int idx = blockIdx.x * blockDim.x + threadIdx.x;
    if (idx >= n_groups * 16) return;
    int g = idx >> 4;
    int q = idx & 15;
    int e0 = g * 4;
    int m  = n_edges - e0;          // edges in this group (1..4)

    int src[4], dst[4];
    if (g_idx_is64) {
        const long long* p = (const long long*)edge_index;
        if (m >= 4) {
            longlong2 s0 = *reinterpret_cast<const longlong2*>(p + e0);
            longlong2 s1 = *reinterpret_cast<const longlong2*>(p + e0 + 2);
            src[0] = (int)s0.x; src[1] = (int)s0.y;
            src[2] = (int)s1.x; src[3] = (int)s1.y;
            if ((n_edges & 1) == 0) {
                longlong2 d0 = *reinterpret_cast<const longlong2*>(p + n_edges + e0);
                longlong2 d1 = *reinterpret_cast<const longlong2*>(p + n_edges + e0 + 2);
                dst[0] = (int)d0.x; dst[1] = (int)d0.y;
                dst[2] = (int)d1.x; dst[3] = (int)d1.y;
            } else {
                #pragma unroll
                for (int i = 0; i < 4; i++) dst[i] = (int)p[(size_t)n_edges + e0 + i];
            }
        } else {
            for (int i = 0; i < m; i++) {
                src[i] = (int)p[e0 + i];
                dst[i] = (int)p[(size_t)n_edges + e0 + i];
            }
        }
    } else {
        const int* p = (const int*)edge_index;
        if (m >= 4) {
            int4 s = *reinterpret_cast<const int4*>(p + e0);
            src[0] = s.x; src[1] = s.y; src[2] = s.z; src[3] = s.w;
            if ((n_edges & 3) == 0) {
                int4 d = *reinterpret_cast<const int4*>(p + n_edges + e0);
                dst[0] = d.x; dst[1] = d.y; dst[2] = d.z; dst[3] = d.w;
            } else {
                #pragma unroll
                for (int i = 0; i < 4; i++) dst[i] = p[n_edges + e0 + i];
            }
        } else {
            for (int i = 0; i < m; i++) {
                src[i] = p[e0 + i];
                dst[i] = p[n_edges + e0 + i];
            }
        }
    }

    if (m >= 4) {
        float4 v[4];
        #pragma unroll
        for (int i = 0; i < 4; i++)
            v[i] = *reinterpret_cast<const float4*>(&g_y[(size_t)src[i] * F_HID + q * 4]);
        #pragma unroll
        for (int i = 0; i < 4; i++) {
            float* addr = &acc[(size_t)dst[i] * F_HID + q * 4];
            asm volatile("red.global.add.v4.f32 [%0], {%1, %2, %3, %4};"
                         :: "l"(addr), "f"(v[i].x), "f"(v[i].y), "f"(v[i].z), "f"(v[i].w)
                         : "memory");
        }
    } else {
        for (int i = 0; i < m; i++) {
            float4 v = *reinterpret_cast<const float4*>(&g_y[(size_t)src[i] * F_HID + q * 4]);
            float* addr = &acc[(size_t)dst[i] * F_HID + q * 4];
            asm volatile("red.global.add.v4.f32 [%0], {%1, %2, %3, %4};"
                         :: "l"(addr), "f"(v.x), "f"(v.y), "f"(v.z), "f"(v.w)
                         : "memory");
        }
    }
}

// ---------------------------------------------------------------------------
// Kernel 5: GEMM2 (in-place on d_out):  out = relu(y + acc + b1) @ W2 + b2.
// Same 128x64 / 8x4 structure as GEMM1; W2 + biases via __ldg.
// ---------------------------------------------------------------------------
__global__ void gemm2_kernel(const float* __restrict__ W2,
                             const float* __restrict__ b1,
                             const float* __restrict__ b2,
                             float* __restrict__ out,
                             int n) {
    __shared__ float shA[GROWS * 68];   // relu(y+acc+b1), [r][k], stride 68

    int tid  = threadIdx.x;
    int row0 = blockIdx.x * GROWS;

    // Build A = relu(y + acc + b1): 128 rows x 16 quads, coalesced
    for (int t = tid; t < GROWS * 16; t += 256) {
        int r = t >> 4;
        int q = t & 15;
        int row = row0 + r;
        float4 o = make_float4(0.f, 0.f, 0.f, 0.f);
        if (row < n) {
            float4 yv = *reinterpret_cast<const float4*>(&g_y[(size_t)row * F_HID + q * 4]);
            float4 av = *reinterpret_cast<const float4*>(&out[(size_t)row * F_HID + q * 4]);
            float4 bv = __ldg(reinterpret_cast<const float4*>(&b1[q * 4]));
            o.x = fmaxf(yv.x + av.x + bv.x, 0.f);
            o.y = fmaxf(yv.y + av.y + bv.y, 0.f);
            o.z = fmaxf(yv.z + av.z + bv.z, 0.f);
            o.w = fmaxf(yv.w + av.w + bv.w, 0.f);
        }
        *reinterpret_cast<float4*>(&shA[r * 68 + q * 4]) = o;
    }
    __syncthreads();

    int ty = tid >> 4;
    int tx = tid & 15;

    float acc[8][4];
    {
        float4 b = __ldg(reinterpret_cast<const float4*>(&b2[tx * 4]));
        #pragma unroll
        for (int i = 0; i < 8; i++) {
            acc[i][0] = b.x; acc[i][1] = b.y; acc[i][2] = b.z; acc[i][3] = b.w;
        }
    }

    const float* ar = &shA[(ty * 8) * 68];
    #pragma unroll 4
    for (int k = 0; k < F_HID; k++) {
        float4 b = __ldg(reinterpret_cast<const float4*>(&W2[k * F_OUT + tx * 4]));
        float a[8];
        #pragma unroll
        for (int i = 0; i < 8; i++) a[i] = ar[i * 68 + k];
        #pragma unroll
        for (int i = 0; i < 8; i++) {
            acc[i][0] = fmaf(a[i], b.x, acc[i][0]);
            acc[i][1] = fmaf(a[i], b.y, acc[i][1]);
            acc[i][2] = fmaf(a[i], b.z, acc[i][2]);
            acc[i][3] = fmaf(a[i], b.w, acc[i][3]);
        }
    }

    #pragma unroll
    for (int i = 0; i < 8; i++) {
        int row = row0 + ty * 8 + i;
        if (row < n) {
            float4 o = make_float4(acc[i][0], acc[i][1], acc[i][2], acc[i][3]);
            *reinterpret_cast<float4*>(&out[(size_t)row * F_OUT + tx * 4]) = o;
        }
    }
}

// ---------------------------------------------------------------------------
extern "C" void kernel_launch(void* const* d_in, const int* in_sizes, int n_in,
                              void* d_out, int out_size) {
    const float* x  = (const float*)d_in[0];   // [100000, 65]
    const void*  ei = d_in[1];                 // [2, E] int64 or int32 (probed)
    const float* W1 = (const float*)d_in[2];   // [65, 64]
    const float* b1 = (const float*)d_in[3];   // [64]
    const float* W2 = (const float*)d_in[4];   // [64, 64]
    const float* b2 = (const float*)d_in[5];   // [64]
    float*       out = (float*)d_out;          // [100000, 64]

    int n_elems = in_sizes[1];
    int n_edges = n_elems / 2;

    // 1) out = 0 + flag reset
    int n4 = (N_NODES * F_HID) / 4;
    zero_out_kernel<<<(n4 + 255) / 256, 256>>>((float4*)out, n4);

    // 2) index dtype probe
    detect_dtype_kernel<<<1024, 256>>>((const long long*)ei, n_elems / 2);

    // 3) y = x @ W1
    int nblk = (N_NODES + GROWS - 1) / GROWS;
    gemm1_kernel<<<nblk, 256>>>(x, W1, N_NODES);

    // 4) out[dst] += y[src]  (4 edges/thread, vector REDs)
    int n_groups = (n_edges + 3) / 4;
    int n_work = n_groups * 16;
    scatter_kernel<<<(n_work + 255) / 256, 256>>>(out, ei, n_edges, n_groups);

    // 5) out = relu(y + out + b1) @ W2 + b2   (in-place)
    gemm2_kernel<<<nblk, 256>>>(W2, b1, b2, out, N_NODES);
}

// round 7
// speedup vs baseline: 2.1972x; 1.1015x over previous
#include <cuda_runtime.h>
#include <cstdint>

#define N_NODES   100000
#define F_IN      65
#define F_HID     64
#define F_OUT     64
#define MAX_EDGES 1600000
#define NCHUNKS   ((N_NODES + 255) / 256)   // 391

// ---- scratch (32.4MB total; memory-checkpoint risk noted) ------------------
__device__ __align__(16) float g_y[(size_t)N_NODES * F_HID];  // y = x @ W1
__device__ int g_srcs[MAX_EDGES];    // CSR: src indices sorted by dst
__device__ int g_cnt[N_NODES];       // counts -> excl prefix -> incl end
__device__ int g_bsum[NCHUNKS];      // per-chunk sums for scan
__device__ int g_idx_is64;

// ---------------------------------------------------------------------------
// Kernel 1: zero counts + reset dtype flag.
// ---------------------------------------------------------------------------
__global__ void zero_cnt_kernel() {
    int i = blockIdx.x * blockDim.x + threadIdx.x;
    if (i == 0) g_idx_is64 = 1;
    if (i < N_NODES) g_cnt[i] = 0;
}

// ---------------------------------------------------------------------------
// Kernel 2: dtype probe — any value outside [0, N_NODES) read as int64 means
// the buffer actually holds int32 indices.
// ---------------------------------------------------------------------------
__global__ void detect_dtype_kernel(const long long* __restrict__ ei, int n64) {
    int stride = gridDim.x * blockDim.x;
    bool bad = false;
    for (int i = blockIdx.x * blockDim.x + threadIdx.x; i < n64; i += stride) {
        long long v = ei[i];
        bad |= (v < 0) | (v >= N_NODES);
    }
    if (__syncthreads_or(bad) && threadIdx.x == 0) g_idx_is64 = 0;
}

// ---------------------------------------------------------------------------
// Kernel 3: GEMM1  y = x @ W1  (R5 proven config: 64x64 tile, 4x4 regs,
// A row-major + W staged in shared).
// ---------------------------------------------------------------------------
__global__ void gemm1_kernel(const float* __restrict__ x,
                             const float* __restrict__ W1,
                             int n) {
    __shared__ float shA[64 * 68];                     // [r][k], stride 68
    __shared__ __align__(16) float shW[F_IN * F_HID];  // [k][j]

    int tid  = threadIdx.x;
    int row0 = blockIdx.x * 64;

    for (int t = tid; t < 64 * F_IN; t += 256) {
        int r = t / F_IN;
        int c = t - r * F_IN;
        int row = row0 + r;
        shA[r * 68 + c] = (row < n) ? x[(size_t)row * F_IN + c] : 0.f;
    }
    for (int t = tid; t < F_IN * F_HID; t += 256) shW[t] = W1[t];
    __syncthreads();

    int ty = tid >> 4;
    int tx = tid & 15;

    float acc[4][4];
    #pragma unroll
    for (int i = 0; i < 4; i++)
        #pragma unroll
        for (int j = 0; j < 4; j++) acc[i][j] = 0.f;

    const float* ar = &shA[(ty * 4) * 68];
    #pragma unroll 5
    for (int k = 0; k < F_IN; k++) {
        float a0 = ar[0 * 68 + k];
        float a1 = ar[1 * 68 + k];
        float a2 = ar[2 * 68 + k];
        float a3 = ar[3 * 68 + k];
        float4 b = *reinterpret_cast<const float4*>(&shW[k * F_HID + tx * 4]);
        acc[0][0] = fmaf(a0, b.x, acc[0][0]); acc[0][1] = fmaf(a0, b.y, acc[0][1]);
        acc[0][2] = fmaf(a0, b.z, acc[0][2]); acc[0][3] = fmaf(a0, b.w, acc[0][3]);
        acc[1][0] = fmaf(a1, b.x, acc[1][0]); acc[1][1] = fmaf(a1, b.y, acc[1][1]);
        acc[1][2] = fmaf(a1, b.z, acc[1][2]); acc[1][3] = fmaf(a1, b.w, acc[1][3]);
        acc[2][0] = fmaf(a2, b.x, acc[2][0]); acc[2][1] = fmaf(a2, b.y, acc[2][1]);
        acc[2][2] = fmaf(a2, b.z, acc[2][2]); acc[2][3] = fmaf(a2, b.w, acc[2][3]);
        acc[3][0] = fmaf(a3, b.x, acc[3][0]); acc[3][1] = fmaf(a3, b.y, acc[3][1]);
        acc[3][2] = fmaf(a3, b.z, acc[3][2]); acc[3][3] = fmaf(a3, b.w, acc[3][3]);
    }

    #pragma unroll
    for (int i = 0; i < 4; i++) {
        int row = row0 + ty * 4 + i;
        if (row < n) {
            float4 o = make_float4(acc[i][0], acc[i][1], acc[i][2], acc[i][3]);
            *reinterpret_cast<float4*>(&g_y[(size_t)row * F_HID + tx * 4]) = o;
        }
    }
}

// ---------------------------------------------------------------------------
// Kernel 4: histogram of dst.
// ---------------------------------------------------------------------------
__global__ void hist_kernel(const void* __restrict__ edge_index, int n_edges) {
    int e = blockIdx.x * blockDim.x + threadIdx.x;
    if (e >= n_edges) return;
    int dst;
    if (g_idx_is64) dst = (int)((const long long*)edge_index)[(size_t)n_edges + e];
    else            dst = ((const int*)edge_index)[n_edges + e];
    atomicAdd(&g_cnt[dst], 1);
}

// ---------------------------------------------------------------------------
// Kernels 5a/5b/5c: 3-level exclusive prefix scan of g_cnt (in place).
// ---------------------------------------------------------------------------
__global__ void chunk_sums_kernel() {
    __shared__ int s[256];
    int b = blockIdx.x, t = threadIdx.x;
    int i = b * 256 + t;
    s[t] = (i < N_NODES) ? g_cnt[i] : 0;
    __syncthreads();
    #pragma unroll
    for (int off = 128; off > 0; off >>= 1) {
        if (t < off) s[t] += s[t + off];
        __syncthreads();
    }
    if (t == 0) g_bsum[b] = s[0];
}

__global__ void scan_bsums_kernel() {
    __shared__ int s[512];
    int t = threadIdx.x;
    int v = (t < NCHUNKS) ? g_bsum[t] : 0;
    s[t] = v;
    __syncthreads();
    #pragma unroll
    for (int off = 1; off < 512; off <<= 1) {
        int add = (t >= off) ? s[t - off] : 0;
        __syncthreads();
        s[t] += add;
        __syncthreads();
    }
    if (t < NCHUNKS) g_bsum[t] = s[t] - v;   // exclusive
}

__global__ void scan_chunks_kernel() {
    __shared__ int s[256];
    int b = blockIdx.x, t = threadIdx.x;
    int i = b * 256 + t;
    int v = (i < N_NODES) ? g_cnt[i] : 0;
    s[t] = v;
    __syncthreads();
    #pragma unroll
    for (int off = 1; off < 256; off <<= 1) {
        int add = (t >= off) ? s[t - off] : 0;
        __syncthreads();
        s[t] += add;
        __syncthreads();
    }
    if (i < N_NODES) g_cnt[i] = g_bsum[b] + s[t] - v;   // exclusive prefix
}

// ---------------------------------------------------------------------------
// Kernel 6: fill CSR. pos = cursor[dst]++ ; g_srcs[pos] = src.
// After this, g_cnt[d] = end offset of node d (inclusive prefix).
// ---------------------------------------------------------------------------
__global__ void fill_kernel(const void* __restrict__ edge_index, int n_edges) {
    int e = blockIdx.x * blockDim.x + threadIdx.x;
    if (e >= n_edges) return;
    int src, dst;
    if (g_idx_is64) {
        const long long* p = (const long long*)edge_index;
        src = (int)p[e];
        dst = (int)p[(size_t)n_edges + e];
    } else {
        const int* p = (const int*)edge_index;
        src = p[e];
        dst = p[n_edges + e];
    }
    int pos = atomicAdd(&g_cnt[dst], 1);
    g_srcs[pos] = src;
}

// ---------------------------------------------------------------------------
// Kernel 7: aggregation (atomic-free). 16-lane group per node: registers
// accumulate sum of y[src] over the node's in-edge list; one 256B write.
// 4-way unrolled for MLP. Writes EVERY row -> no zero pass needed.
// ---------------------------------------------------------------------------
__global__ void aggregate_kernel(float* __restrict__ out, int n_nodes) {
    int gid = blockIdx.x * (blockDim.x >> 4) + (threadIdx.x >> 4);
    int q   = threadIdx.x & 15;
    if (gid >= n_nodes) return;

    int start = gid ? g_cnt[gid - 1] : 0;
    int end   = g_cnt[gid];

    float4 v = make_float4(0.f, 0.f, 0.f, 0.f);
    int e = start;
    for (; e + 4 <= end; e += 4) {
        int s0 = g_srcs[e + 0];
        int s1 = g_srcs[e + 1];
        int s2 = g_srcs[e + 2];
        int s3 = g_srcs[e + 3];
        float4 a = *reinterpret_cast<const float4*>(&g_y[(size_t)s0 * F_HID + q * 4]);
        float4 b = *reinterpret_cast<const float4*>(&g_y[(size_t)s1 * F_HID + q * 4]);
        float4 c = *reinterpret_cast<const float4*>(&g_y[(size_t)s2 * F_HID + q * 4]);
        float4 d = *reinterpret_cast<const float4*>(&g_y[(size_t)s3 * F_HID + q * 4]);
        v.x += (a.x + b.x) + (c.x + d.x);
        v.y += (a.y + b.y) + (c.y + d.y);
        v.z += (a.z + b.z) + (c.z + d.z);
        v.w += (a.w + b.w) + (c.w + d.w);
    }
    for (; e < end; e++) {
        int s = g_srcs[e];
        float4 a = *reinterpret_cast<const float4*>(&g_y[(size_t)s * F_HID + q * 4]);
        v.x += a.x; v.y += a.y; v.z += a.z; v.w += a.w;
    }

    *reinterpret_cast<float4*>(&out[(size_t)gid * F_HID + q * 4]) = v;
}

// ---------------------------------------------------------------------------
// Kernel 8: GEMM2 (in-place on d_out): out = relu(y + acc + b1) @ W2 + b2.
// R5 proven config.
// ---------------------------------------------------------------------------
__global__ void gemm2_kernel(const float* __restrict__ W2,
                             const float* __restrict__ b1,
                             const float* __restrict__ b2,
                             float* __restrict__ out,
                             int n) {
    __shared__ __align__(16) float shA[64 * 68];
    __shared__ __align__(16) float shW[F_HID * F_OUT];
    __shared__ float sb1[F_HID];
    __shared__ float sb2[F_OUT];

    int tid  = threadIdx.x;
    int row0 = blockIdx.x * 64;

    if (tid < F_HID) { sb1[tid] = b1[tid]; sb2[tid] = b2[tid]; }
    for (int t = tid; t < F_HID * F_OUT; t += 256) shW[t] = W2[t];
    __syncthreads();

    for (int t = tid; t < 64 * 16; t += 256) {
        int r = t >> 4;
        int q = t & 15;
        int row = row0 + r;
        float4 o = make_float4(0.f, 0.f, 0.f, 0.f);
        if (row < n) {
            float4 yv = *reinterpret_cast<const float4*>(&g_y[(size_t)row * F_HID + q * 4]);
            float4 av = *reinterpret_cast<const float4*>(&out[(size_t)row * F_HID + q * 4]);
            float4 bv = *reinterpret_cast<const float4*>(&sb1[q * 4]);
            o.x = fmaxf(yv.x + av.x + bv.x, 0.f);
            o.y = fmaxf(yv.y + av.y + bv.y, 0.f);
            o.z = fmaxf(yv.z + av.z + bv.z, 0.f);
            o.w = fmaxf(yv.w + av.w + bv.w, 0.f);
        }
        *reinterpret_cast<float4*>(&shA[r * 68 + q * 4]) = o;
    }
    __syncthreads();

    int ty = tid >> 4;
    int tx = tid & 15;

    float acc[4][4];
    {
        float4 b = *reinterpret_cast<const float4*>(&sb2[tx * 4]);
        #pragma unroll
        for (int i = 0; i < 4; i++) {
            acc[i][0] = b.x; acc[i][1] = b.y; acc[i][2] = b.z; acc[i][3] = b.w;
        }
    }

    const float* ar = &shA[(ty * 4) * 68];
    #pragma unroll 8
    for (int k = 0; k < F_HID; k++) {
        float a0 = ar[0 * 68 + k];
        float a1 = ar[1 * 68 + k];
        float a2 = ar[2 * 68 + k];
        float a3 = ar[3 * 68 + k];
        float4 b = *reinterpret_cast<const float4*>(&shW[k * F_OUT + tx * 4]);
        acc[0][0] = fmaf(a0, b.x, acc[0][0]); acc[0][1] = fmaf(a0, b.y, acc[0][1]);
        acc[0][2] = fmaf(a0, b.z, acc[0][2]); acc[0][3] = fmaf(a0, b.w, acc[0][3]);
        acc[1][0] = fmaf(a1, b.x, acc[1][0]); acc[1][1] = fmaf(a1, b.y, acc[1][1]);
        acc[1][2] = fmaf(a1, b.z, acc[1][2]); acc[1][3] = fmaf(a1, b.w, acc[1][3]);
        acc[2][0] = fmaf(a2, b.x, acc[2][0]); acc[2][1] = fmaf(a2, b.y, acc[2][1]);
        acc[2][2] = fmaf(a2, b.z, acc[2][2]); acc[2][3] = fmaf(a2, b.w, acc[2][3]);
        acc[3][0] = fmaf(a3, b.x, acc[3][0]); acc[3][1] = fmaf(a3, b.y, acc[3][1]);
        acc[3][2] = fmaf(a3, b.z, acc[3][2]); acc[3][3] = fmaf(a3, b.w, acc[3][3]);
    }

    #pragma unroll
    for (int i = 0; i < 4; i++) {
        int row = row0 + ty * 4 + i;
        if (row < n) {
            float4 o = make_float4(acc[i][0], acc[i][1], acc[i][2], acc[i][3]);
            *reinterpret_cast<float4*>(&out[(size_t)row * F_OUT + tx * 4]) = o;
        }
    }
}

// ---------------------------------------------------------------------------
extern "C" void kernel_launch(void* const* d_in, const int* in_sizes, int n_in,
                              void* d_out, int out_size) {
    const float* x  = (const float*)d_in[0];   // [100000, 65]
    const void*  ei = d_in[1];                 // [2, E] int64 or int32 (probed)
    const float* W1 = (const float*)d_in[2];   // [65, 64]
    const float* b1 = (const float*)d_in[3];   // [64]
    const float* W2 = (const float*)d_in[4];   // [64, 64]
    const float* b2 = (const float*)d_in[5];   // [64]
    float*       out = (float*)d_out;          // [100000, 64]

    int n_elems = in_sizes[1];
    int n_edges = n_elems / 2;
    if (n_edges > MAX_EDGES) n_edges = MAX_EDGES;

    // 1) zero counts + flag reset
    zero_cnt_kernel<<<(N_NODES + 255) / 256, 256>>>();

    // 2) index dtype probe
    detect_dtype_kernel<<<1024, 256>>>((const long long*)ei, n_elems / 2);

    // 3) y = x @ W1
    int nblk = (N_NODES + 63) / 64;
    gemm1_kernel<<<nblk, 256>>>(x, W1, N_NODES);

    // 4) CSR build: histogram -> exclusive scan -> fill
    int eblk = (n_edges + 255) / 256;
    hist_kernel<<<eblk, 256>>>(ei, n_edges);
    chunk_sums_kernel<<<NCHUNKS, 256>>>();
    scan_bsums_kernel<<<1, 512>>>();
    scan_chunks_kernel<<<NCHUNKS, 256>>>();
    fill_kernel<<<eblk, 256>>>(ei, n_edges);

    // 5) atomic-free aggregation: out[n] = sum_{src in-edges} y[src]
    int groups_per_block = 256 / 16;
    int ablk = (N_NODES + groups_per_block - 1) / groups_per_block;
    aggregate_kernel<<<ablk, 256>>>(out, N_NODES);

    // 6) out = relu(y + out + b1) @ W2 + b2   (in-place)
    gemm2_kernel<<<nblk, 256>>>(W2, b1, b2, out, N_NODES);
}